// round 10
// baseline (speedup 1.0000x reference)
#include <cuda_runtime.h>
#include <cuda.h>
#include <cstdint>

#define H    128
#define TM   128
#define KC   16
#define NTHR 256

// ---------------- device scratch (allocation-free) ----------------
__device__ float g_agg[50048 * H];
__device__ float g_P[50048 * H];    // x @ We1[0:128]    (row-part)
__device__ float g_Q[50048 * H];    // x @ We1[128:256]  (col-part)

// ---------------- packed f32x2 helpers ----------------
__device__ __forceinline__ uint64_t pk2s(float a) {            // splat {a,a}
    uint64_t r;
    asm("mov.b64 %0, {%1, %1};" : "=l"(r) : "f"(a));
    return r;
}
__device__ __forceinline__ uint64_t pk2f(float a, float b) {   // pack {a,b}
    uint64_t r;
    asm("mov.b64 %0, {%1, %2};" : "=l"(r) : "f"(a), "f"(b));
    return r;
}
__device__ __forceinline__ float2 upk(uint64_t v) {
    float2 f;
    asm("mov.b64 {%0, %1}, %2;" : "=f"(f.x), "=f"(f.y) : "l"(v));
    return f;
}
__device__ __forceinline__ void ffma2(uint64_t& d, uint64_t a, uint64_t b) {
    asm("fma.rn.f32x2 %0, %1, %2, %0;" : "+l"(d) : "l"(a), "l"(b));
}

__device__ __forceinline__ void red_add_v4(float* addr, float a, float b, float c, float d) {
    asm volatile("red.global.add.v4.f32 [%0], {%1,%2,%3,%4};"
                 :: "l"(addr), "f"(a), "f"(b), "f"(c), "f"(d) : "memory");
}

__global__ void zero_agg_kernel(int n4) {
    int i = blockIdx.x * blockDim.x + threadIdx.x;
    if (i < n4) ((float4*)g_agg)[i] = make_float4(0.f, 0.f, 0.f, 0.f);
}

// ---------------------------------------------------------------------------
// prep_pq: P = x @ We1[0:128,:],  Q = x @ We1[128:256,:]
// ---------------------------------------------------------------------------
__global__ void __launch_bounds__(NTHR, 2)
prep_pq_kernel(const float* __restrict__ x, const float* __restrict__ We1, int nN)
{
    extern __shared__ float sm[];
    float* Bs = sm;                 // [KC][H]
    float* As = sm + KC * H;        // [KC][TM]

    const int tid = threadIdx.x;
    const int tx  = tid & 15;
    const int ty  = tid >> 4;
    const int n0  = blockIdx.x * TM;

    const float* W = We1 + (size_t)(blockIdx.y * H) * H;
    float* outbuf  = blockIdx.y ? g_Q : g_P;

    const int le = tid >> 1;
    const int lh = (tid & 1) * 8;
    const float* aX = x + (size_t)min(n0 + le, nN - 1) * H;

    const int bk = tid >> 4;
    const int bh = (tid & 15) * 8;

    uint64_t acc2[8][4];
    #pragma unroll
    for (int i = 0; i < 8; i++)
        #pragma unroll
        for (int j = 0; j < 4; j++) acc2[i][j] = 0ull;

    for (int kc = 0; kc < 8; kc++) {
        const int k0 = kc * KC;
        float4 a0 = *(const float4*)(aX + k0 + lh);
        float4 a1 = *(const float4*)(aX + k0 + lh + 4);
        const float* wrow = W + (size_t)(k0 + bk) * H + bh;
        float4 b0 = *(const float4*)(wrow);
        float4 b1 = *(const float4*)(wrow + 4);
        __syncthreads();
        As[(lh + 0) * TM + le] = a0.x; As[(lh + 1) * TM + le] = a0.y;
        As[(lh + 2) * TM + le] = a0.z; As[(lh + 3) * TM + le] = a0.w;
        As[(lh + 4) * TM + le] = a1.x; As[(lh + 5) * TM + le] = a1.y;
        As[(lh + 6) * TM + le] = a1.z; As[(lh + 7) * TM + le] = a1.w;
        *(float4*)&Bs[bk * H + bh]     = b0;
        *(float4*)&Bs[bk * H + bh + 4] = b1;
        __syncthreads();
        #pragma unroll
        for (int kk = 0; kk < KC; kk++) {
            float af[8];
            *(float4*)&af[0] = *(const float4*)&As[kk * TM + ty * 8];
            *(float4*)&af[4] = *(const float4*)&As[kk * TM + ty * 8 + 4];
            const uint64_t* bp = (const uint64_t*)&Bs[kk * H + tx * 8];
            uint64_t bb0 = bp[0], bb1 = bp[1], bb2 = bp[2], bb3 = bp[3];
            #pragma unroll
            for (int i = 0; i < 8; i++) {
                uint64_t a2 = pk2s(af[i]);
                ffma2(acc2[i][0], a2, bb0);
                ffma2(acc2[i][1], a2, bb1);
                ffma2(acc2[i][2], a2, bb2);
                ffma2(acc2[i][3], a2, bb3);
            }
        }
    }

    #pragma unroll
    for (int i = 0; i < 8; i++) {
        const int r = ty * 8 + i;
        if (n0 + r < nN) {
            float* dst = outbuf + (size_t)(n0 + r) * H + tx * 8;
            float2 v0 = upk(acc2[i][0]), v1 = upk(acc2[i][1]);
            float2 v2 = upk(acc2[i][2]), v3 = upk(acc2[i][3]);
            *(float4*)(dst)     = make_float4(v0.x, v0.y, v1.x, v1.y);
            *(float4*)(dst + 4) = make_float4(v2.x, v2.y, v3.x, v3.y);
        }
    }
}

// ---------------------------------------------------------------------------
// Edge pass:
//   hidden = relu( ea @ We1_c + P[row] + Q[col] + b1 )
//   msg    = hidden @ We2 + b2   -> red.add.v4 scatter into g_agg[col]
// ---------------------------------------------------------------------------
__global__ void __launch_bounds__(NTHR, 2)
edge_kernel(const float* __restrict__ ea, const int* __restrict__ eidx,
            const float* __restrict__ We1, const float* __restrict__ be1,
            const float* __restrict__ We2, const float* __restrict__ be2,
            int nE)
{
    extern __shared__ float sm[];
    float* Bs  = sm;                       // [KC][H]
    float* Hsm = sm + KC * H;              // [TM][H+4]
    float* As  = Hsm + TM * (H + 4);       // [KC][TM]
    __shared__ int rowi[TM];
    __shared__ int coli[TM];

    const int tid = threadIdx.x;
    const int tx  = tid & 15;
    const int ty  = tid >> 4;
    const int e0  = blockIdx.x * TM;

    if (tid < TM) {
        int ec = min(e0 + tid, nE - 1);
        rowi[tid] = eidx[ec];
        coli[tid] = eidx[nE + ec];
    }
    __syncthreads();

    const int le = tid >> 1;
    const int lh = (tid & 1) * 8;
    const float* aEa = ea + (size_t)min(e0 + le, nE - 1) * H;

    const int bk = tid >> 4;
    const int bh = (tid & 15) * 8;

    const float* We1c = We1 + (size_t)256 * H;   // rows 256..383: edge_attr part

    uint64_t acc2[8][4];
    {
        const float2* bb = (const float2*)(be1 + tx * 8);
        uint64_t b2[4];
        #pragma unroll
        for (int j = 0; j < 4; j++) b2[j] = pk2f(bb[j].x, bb[j].y);
        #pragma unroll
        for (int i = 0; i < 8; i++)
            #pragma unroll
            for (int j = 0; j < 4; j++) acc2[i][j] = b2[j];
    }

    // ---------------- Stage 1: ea @ We1_c  (K=128) ----------------
    for (int kc = 0; kc < 8; kc++) {
        const int k0 = kc * KC;
        float4 a0 = *(const float4*)(aEa + k0 + lh);
        float4 a1 = *(const float4*)(aEa + k0 + lh + 4);
        const float* wrow = We1c + (size_t)(k0 + bk) * H + bh;
        float4 b0 = *(const float4*)(wrow);
        float4 b1 = *(const float4*)(wrow + 4);
        __syncthreads();
        As[(lh + 0) * TM + le] = a0.x; As[(lh + 1) * TM + le] = a0.y;
        As[(lh + 2) * TM + le] = a0.z; As[(lh + 3) * TM + le] = a0.w;
        As[(lh + 4) * TM + le] = a1.x; As[(lh + 5) * TM + le] = a1.y;
        As[(lh + 6) * TM + le] = a1.z; As[(lh + 7) * TM + le] = a1.w;
        *(float4*)&Bs[bk * H + bh]     = b0;
        *(float4*)&Bs[bk * H + bh + 4] = b1;
        __syncthreads();
        #pragma unroll
        for (int kk = 0; kk < KC; kk++) {
            float af[8];
            *(float4*)&af[0] = *(const float4*)&As[kk * TM + ty * 8];
            *(float4*)&af[4] = *(const float4*)&As[kk * TM + ty * 8 + 4];
            const uint64_t* bp = (const uint64_t*)&Bs[kk * H + tx * 8];
            uint64_t bb0 = bp[0], bb1 = bp[1], bb2 = bp[2], bb3 = bp[3];
            #pragma unroll
            for (int i = 0; i < 8; i++) {
                uint64_t a2 = pk2s(af[i]);
                ffma2(acc2[i][0], a2, bb0);
                ffma2(acc2[i][1], a2, bb1);
                ffma2(acc2[i][2], a2, bb2);
                ffma2(acc2[i][3], a2, bb3);
            }
        }
    }

    // ---------------- gather-add P[row] + Q[col], ReLU -> Hsm ----------------
    __syncthreads();
    #pragma unroll
    for (int i = 0; i < 8; i++) {
        const int r = ty * 8 + i;
        const float* pp = g_P + (size_t)rowi[r] * H + tx * 8;
        const float* qq = g_Q + (size_t)coli[r] * H + tx * 8;
        float4 p0 = *(const float4*)(pp);
        float4 p1 = *(const float4*)(pp + 4);
        float4 q0 = *(const float4*)(qq);
        float4 q1 = *(const float4*)(qq + 4);
        float2 v0 = upk(acc2[i][0]), v1 = upk(acc2[i][1]);
        float2 v2 = upk(acc2[i][2]), v3 = upk(acc2[i][3]);
        float* hp = &Hsm[r * (H + 4) + tx * 8];
        float4 h0, h1;
        h0.x = fmaxf(v0.x + p0.x + q0.x, 0.f);
        h0.y = fmaxf(v0.y + p0.y + q0.y, 0.f);
        h0.z = fmaxf(v1.x + p0.z + q0.z, 0.f);
        h0.w = fmaxf(v1.y + p0.w + q0.w, 0.f);
        h1.x = fmaxf(v2.x + p1.x + q1.x, 0.f);
        h1.y = fmaxf(v2.y + p1.y + q1.y, 0.f);
        h1.z = fmaxf(v3.x + p1.z + q1.z, 0.f);
        h1.w = fmaxf(v3.y + p1.w + q1.w, 0.f);
        *(float4*)(hp)     = h0;
        *(float4*)(hp + 4) = h1;
    }
    {
        const float2* bb = (const float2*)(be2 + tx * 8);
        uint64_t b2[4];
        #pragma unroll
        for (int j = 0; j < 4; j++) b2[j] = pk2f(bb[j].x, bb[j].y);
        #pragma unroll
        for (int i = 0; i < 8; i++)
            #pragma unroll
            for (int j = 0; j < 4; j++) acc2[i][j] = b2[j];
    }
    __syncthreads();

    // ---------------- Stage 2: hidden @ We2  (K=128) ----------------
    for (int kc = 0; kc < 8; kc++) {
        const float* wrow = We2 + (size_t)(kc * KC + bk) * H + bh;
        float4 b0 = *(const float4*)(wrow);
        float4 b1 = *(const float4*)(wrow + 4);
        __syncthreads();
        *(float4*)&Bs[bk * H + bh]     = b0;
        *(float4*)&Bs[bk * H + bh + 4] = b1;
        __syncthreads();
        #pragma unroll
        for (int kk = 0; kk < KC; kk++) {
            const int k = kc * KC + kk;
            const uint64_t* bp = (const uint64_t*)&Bs[kk * H + tx * 8];
            uint64_t bb0 = bp[0], bb1 = bp[1], bb2 = bp[2], bb3 = bp[3];
            #pragma unroll
            for (int i = 0; i < 8; i++) {
                uint64_t a2 = pk2s(Hsm[(ty * 8 + i) * (H + 4) + k]);
                ffma2(acc2[i][0], a2, bb0);
                ffma2(acc2[i][1], a2, bb1);
                ffma2(acc2[i][2], a2, bb2);
                ffma2(acc2[i][3], a2, bb3);
            }
        }
    }

    // ---------------- scatter-add ----------------
    #pragma unroll
    for (int i = 0; i < 8; i++) {
        const int r = ty * 8 + i;
        if (e0 + r < nE) {
            float* dst = g_agg + (size_t)coli[r] * H + tx * 8;
            float2 v0 = upk(acc2[i][0]), v1 = upk(acc2[i][1]);
            float2 v2 = upk(acc2[i][2]), v3 = upk(acc2[i][3]);
            red_add_v4(dst,     v0.x, v0.y, v1.x, v1.y);
            red_add_v4(dst + 4, v2.x, v2.y, v3.x, v3.y);
        }
    }
}

// ---------------------------------------------------------------------------
// Node pass: out = MLP2(concat(x, agg))
// ---------------------------------------------------------------------------
__global__ void __launch_bounds__(NTHR, 2)
node_kernel(const float* __restrict__ x,
            const float* __restrict__ Wn1, const float* __restrict__ bn1,
            const float* __restrict__ Wn2, const float* __restrict__ bn2,
            float* __restrict__ out, int nN)
{
    extern __shared__ float sm[];
    float* Bs  = sm;
    float* Hsm = sm + KC * H;
    float* As  = Hsm + TM * (H + 4);

    const int tid = threadIdx.x;
    const int tx  = tid & 15;
    const int ty  = tid >> 4;
    const int n0  = blockIdx.x * TM;

    const int le = tid >> 1;
    const int lh = (tid & 1) * 8;
    const size_t nrow = (size_t)min(n0 + le, nN - 1) * H;
    const float* aX = x + nrow;
    const float* aG = g_agg + nrow;

    const int bk = tid >> 4;
    const int bh = (tid & 15) * 8;

    uint64_t acc2[8][4];
    {
        const float2* bb = (const float2*)(bn1 + tx * 8);
        uint64_t b2[4];
        #pragma unroll
        for (int j = 0; j < 4; j++) b2[j] = pk2f(bb[j].x, bb[j].y);
        #pragma unroll
        for (int i = 0; i < 8; i++)
            #pragma unroll
            for (int j = 0; j < 4; j++) acc2[i][j] = b2[j];
    }

    for (int kc = 0; kc < 16; kc++) {
        const int k0 = (kc & 7) * KC;
        const float* abase = (kc < 8) ? aX : aG;
        float4 a0 = *(const float4*)(abase + k0 + lh);
        float4 a1 = *(const float4*)(abase + k0 + lh + 4);
        const float* wrow = Wn1 + (size_t)(kc * KC + bk) * H + bh;
        float4 b0 = *(const float4*)(wrow);
        float4 b1 = *(const float4*)(wrow + 4);
        __syncthreads();
        As[(lh + 0) * TM + le] = a0.x; As[(lh + 1) * TM + le] = a0.y;
        As[(lh + 2) * TM + le] = a0.z; As[(lh + 3) * TM + le] = a0.w;
        As[(lh + 4) * TM + le] = a1.x; As[(lh + 5) * TM + le] = a1.y;
        As[(lh + 6) * TM + le] = a1.z; As[(lh + 7) * TM + le] = a1.w;
        *(float4*)&Bs[bk * H + bh]     = b0;
        *(float4*)&Bs[bk * H + bh + 4] = b1;
        __syncthreads();
        #pragma unroll
        for (int kk = 0; kk < KC; kk++) {
            float af[8];
            *(float4*)&af[0] = *(const float4*)&As[kk * TM + ty * 8];
            *(float4*)&af[4] = *(const float4*)&As[kk * TM + ty * 8 + 4];
            const uint64_t* bp = (const uint64_t*)&Bs[kk * H + tx * 8];
            uint64_t bb0 = bp[0], bb1 = bp[1], bb2 = bp[2], bb3 = bp[3];
            #pragma unroll
            for (int i = 0; i < 8; i++) {
                uint64_t a2 = pk2s(af[i]);
                ffma2(acc2[i][0], a2, bb0);
                ffma2(acc2[i][1], a2, bb1);
                ffma2(acc2[i][2], a2, bb2);
                ffma2(acc2[i][3], a2, bb3);
            }
        }
    }

    __syncthreads();
    #pragma unroll
    for (int i = 0; i < 8; i++) {
        const int r = ty * 8 + i;
        float2 v0 = upk(acc2[i][0]), v1 = upk(acc2[i][1]);
        float2 v2 = upk(acc2[i][2]), v3 = upk(acc2[i][3]);
        float* hp = &Hsm[r * (H + 4) + tx * 8];
        float4 h0, h1;
        h0.x = fmaxf(v0.x, 0.f); h0.y = fmaxf(v0.y, 0.f);
        h0.z = fmaxf(v1.x, 0.f); h0.w = fmaxf(v1.y, 0.f);
        h1.x = fmaxf(v2.x, 0.f); h1.y = fmaxf(v2.y, 0.f);
        h1.z = fmaxf(v3.x, 0.f); h1.w = fmaxf(v3.y, 0.f);
        *(float4*)(hp)     = h0;
        *(float4*)(hp + 4) = h1;
    }
    {
        const float2* bb = (const float2*)(bn2 + tx * 8);
        uint64_t b2[4];
        #pragma unroll
        for (int j = 0; j < 4; j++) b2[j] = pk2f(bb[j].x, bb[j].y);
        #pragma unroll
        for (int i = 0; i < 8; i++)
            #pragma unroll
            for (int j = 0; j < 4; j++) acc2[i][j] = b2[j];
    }
    __syncthreads();

    for (int kc = 0; kc < 8; kc++) {
        const float* wrow = Wn2 + (size_t)(kc * KC + bk) * H + bh;
        float4 b0 = *(const float4*)(wrow);
        float4 b1 = *(const float4*)(wrow + 4);
        __syncthreads();
        *(float4*)&Bs[bk * H + bh]     = b0;
        *(float4*)&Bs[bk * H + bh + 4] = b1;
        __syncthreads();
        #pragma unroll
        for (int kk = 0; kk < KC; kk++) {
            const int k = kc * KC + kk;
            const uint64_t* bp = (const uint64_t*)&Bs[kk * H + tx * 8];
            uint64_t bb0 = bp[0], bb1 = bp[1], bb2 = bp[2], bb3 = bp[3];
            #pragma unroll
            for (int i = 0; i < 8; i++) {
                uint64_t a2 = pk2s(Hsm[(ty * 8 + i) * (H + 4) + k]);
                ffma2(acc2[i][0], a2, bb0);
                ffma2(acc2[i][1], a2, bb1);
                ffma2(acc2[i][2], a2, bb2);
                ffma2(acc2[i][3], a2, bb3);
            }
        }
    }

    #pragma unroll
    for (int i = 0; i < 8; i++) {
        const int r = ty * 8 + i;
        if (n0 + r < nN) {
            float* dst = out + (size_t)(n0 + r) * H + tx * 8;
            float2 v0 = upk(acc2[i][0]), v1 = upk(acc2[i][1]);
            float2 v2 = upk(acc2[i][2]), v3 = upk(acc2[i][3]);
            *(float4*)(dst)     = make_float4(v0.x, v0.y, v1.x, v1.y);
            *(float4*)(dst + 4) = make_float4(v2.x, v2.y, v3.x, v3.y);
        }
    }
}

extern "C" void kernel_launch(void* const* d_in, const int* in_sizes, int n_in,
                              void* d_out, int out_size)
{
    const float* x    = (const float*)d_in[0];
    const int*   eidx = (const int*)d_in[1];
    const float* ea   = (const float*)d_in[2];
    const float* We1  = (const float*)d_in[3];
    const float* be1  = (const float*)d_in[4];
    const float* We2  = (const float*)d_in[5];
    const float* be2  = (const float*)d_in[6];
    const float* Wn1  = (const float*)d_in[7];
    const float* bn1  = (const float*)d_in[8];
    const float* Wn2  = (const float*)d_in[9];
    const float* bn2  = (const float*)d_in[10];
    float* out = (float*)d_out;

    const int nN = in_sizes[0] / H;
    const int nE = in_sizes[1] / 2;

    const int big_smem  = (KC * H + TM * (H + 4) + KC * TM) * (int)sizeof(float);
    const int prep_smem = (KC * H + KC * TM) * (int)sizeof(float);
    cudaFuncSetAttribute(edge_kernel, cudaFuncAttributeMaxDynamicSharedMemorySize, big_smem);
    cudaFuncSetAttribute(node_kernel, cudaFuncAttributeMaxDynamicSharedMemorySize, big_smem);
    cudaFuncSetAttribute(prep_pq_kernel, cudaFuncAttributeMaxDynamicSharedMemorySize, prep_smem);

    const int n4 = nN * H / 4;
    zero_agg_kernel<<<(n4 + 255) / 256, 256>>>(n4);

    dim3 pq_grid((nN + TM - 1) / TM, 2);
    prep_pq_kernel<<<pq_grid, NTHR, prep_smem>>>(x, We1, nN);

    edge_kernel<<<(nE + TM - 1) / TM, NTHR, big_smem>>>(ea, eidx, We1, be1, We2, be2, nE);
    node_kernel<<<(nN + TM - 1) / TM, NTHR, big_smem>>>(x, Wn1, bn1, Wn2, bn2, out, nN);
}

// round 11
// speedup vs baseline: 2.4785x; 2.4785x over previous
#include <cuda_runtime.h>
#include <cuda.h>
#include <cstdint>

#define H    128
#define TM   128
#define KC   16
#define NTHR 256

// ---------------- device scratch (allocation-free) ----------------
__device__ float g_aggH[50048 * H];   // segment-sum of hidden vectors
__device__ float g_deg[50048];        // in-degree (float)
__device__ float g_P[50048 * H];      // x @ We1[0:128]
__device__ float g_Q[50048 * H];      // x @ We1[128:256]
__device__ float g_Wp[H * H];         // We2 @ Wn1[128:256]
__device__ float g_C[H];              // be2 @ Wn1[128:256]

__device__ __forceinline__ void red_add_v4(float* addr, float a, float b, float c, float d) {
    asm volatile("red.global.add.v4.f32 [%0], {%1,%2,%3,%4};"
                 :: "l"(addr), "f"(a), "f"(b), "f"(c), "f"(d) : "memory");
}
__device__ __forceinline__ void red_add_f32(float* addr, float v) {
    asm volatile("red.global.add.f32 [%0], %1;" :: "l"(addr), "f"(v) : "memory");
}

__global__ void zero_kernel(int n4, int nd4) {
    int i = blockIdx.x * blockDim.x + threadIdx.x;
    if (i < n4)            ((float4*)g_aggH)[i] = make_float4(0.f, 0.f, 0.f, 0.f);
    else if (i < n4 + nd4) ((float4*)g_deg)[i - n4] = make_float4(0.f, 0.f, 0.f, 0.f);
}

// ---------------------------------------------------------------------------
// prep: y=0 -> P = x@We1[0:128]; y=1 -> Q = x@We1[128:256];
//       y=2 (block x==0 only) -> W' = We2@Wn1_bot, C = be2@Wn1_bot
// ---------------------------------------------------------------------------
__global__ void __launch_bounds__(NTHR, 2)
prep_kernel(const float* __restrict__ x, const float* __restrict__ We1,
            const float* __restrict__ We2, const float* __restrict__ Wn1,
            const float* __restrict__ be2, int nN)
{
    if (blockIdx.y == 2 && blockIdx.x > 0) return;

    extern __shared__ float sm[];
    float* Bs = sm;                 // [KC][H]
    float* As = sm + KC * H;        // [KC][TM]

    const int tid = threadIdx.x;
    const int tx  = tid & 15;
    const int ty  = tid >> 4;
    const int n0  = blockIdx.x * TM;

    const float* Asrc;
    const float* W;
    float* outbuf;
    int rows;
    if (blockIdx.y == 0)      { Asrc = x;   W = We1;                    outbuf = g_P;  rows = nN; }
    else if (blockIdx.y == 1) { Asrc = x;   W = We1 + (size_t)H * H;    outbuf = g_Q;  rows = nN; }
    else                      { Asrc = We2; W = Wn1 + (size_t)H * H;    outbuf = g_Wp; rows = H;  }

    const int le = tid >> 1;
    const int lh = (tid & 1) * 8;
    const float* aX = Asrc + (size_t)min(n0 + le, rows - 1) * H;

    const int bk = tid >> 4;
    const int bh = (tid & 15) * 8;

    float acc[8][8];
    #pragma unroll
    for (int i = 0; i < 8; i++)
        #pragma unroll
        for (int j = 0; j < 8; j++) acc[i][j] = 0.f;

    for (int kc = 0; kc < 8; kc++) {
        const int k0 = kc * KC;
        float4 a0 = *(const float4*)(aX + k0 + lh);
        float4 a1 = *(const float4*)(aX + k0 + lh + 4);
        const float* wrow = W + (size_t)(k0 + bk) * H + bh;
        float4 b0 = *(const float4*)(wrow);
        float4 b1 = *(const float4*)(wrow + 4);
        __syncthreads();
        As[(lh + 0) * TM + le] = a0.x; As[(lh + 1) * TM + le] = a0.y;
        As[(lh + 2) * TM + le] = a0.z; As[(lh + 3) * TM + le] = a0.w;
        As[(lh + 4) * TM + le] = a1.x; As[(lh + 5) * TM + le] = a1.y;
        As[(lh + 6) * TM + le] = a1.z; As[(lh + 7) * TM + le] = a1.w;
        *(float4*)&Bs[bk * H + bh]     = b0;
        *(float4*)&Bs[bk * H + bh + 4] = b1;
        __syncthreads();
        #pragma unroll
        for (int kk = 0; kk < KC; kk++) {
            float af[8], bf[8];
            *(float4*)&af[0] = *(const float4*)&As[kk * TM + ty * 8];
            *(float4*)&af[4] = *(const float4*)&As[kk * TM + ty * 8 + 4];
            *(float4*)&bf[0] = *(const float4*)&Bs[kk * H + tx * 8];
            *(float4*)&bf[4] = *(const float4*)&Bs[kk * H + tx * 8 + 4];
            #pragma unroll
            for (int i = 0; i < 8; i++)
                #pragma unroll
                for (int j = 0; j < 8; j++)
                    acc[i][j] = fmaf(af[i], bf[j], acc[i][j]);
        }
    }

    #pragma unroll
    for (int i = 0; i < 8; i++) {
        const int r = ty * 8 + i;
        if (n0 + r < rows) {
            float* dst = outbuf + (size_t)(n0 + r) * H + tx * 8;
            *(float4*)(dst)     = make_float4(acc[i][0], acc[i][1], acc[i][2], acc[i][3]);
            *(float4*)(dst + 4) = make_float4(acc[i][4], acc[i][5], acc[i][6], acc[i][7]);
        }
    }

    // C = be2 @ Wn1_bot
    if (blockIdx.y == 2 && tid < H) {
        float s = 0.f;
        #pragma unroll 8
        for (int m = 0; m < H; m++)
            s = fmaf(be2[m], Wn1[(size_t)(H + m) * H + tid], s);
        g_C[tid] = s;
    }
}

// ---------------------------------------------------------------------------
// Edge pass (stage-1 only):
//   hidden = relu( ea @ We1_c + P[row] + Q[col] + b1 )
//   red.add hidden into g_aggH[col]; red.add 1.0 into g_deg[col]
// ---------------------------------------------------------------------------
__global__ void __launch_bounds__(NTHR, 2)
edge_kernel(const float* __restrict__ ea, const int* __restrict__ eidx,
            const float* __restrict__ We1, const float* __restrict__ be1,
            int nE)
{
    extern __shared__ float sm[];
    float* Bs = sm;                 // [KC][H]
    float* As = sm + KC * H;        // [KC][TM]
    __shared__ int rowi[TM];
    __shared__ int coli[TM];

    const int tid = threadIdx.x;
    const int tx  = tid & 15;
    const int ty  = tid >> 4;
    const int e0  = blockIdx.x * TM;

    if (tid < TM) {
        int ec = min(e0 + tid, nE - 1);
        rowi[tid] = eidx[ec];
        coli[tid] = eidx[nE + ec];
    }
    __syncthreads();

    const int le = tid >> 1;
    const int lh = (tid & 1) * 8;
    const float* aEa = ea + (size_t)min(e0 + le, nE - 1) * H;

    const int bk = tid >> 4;
    const int bh = (tid & 15) * 8;

    const float* We1c = We1 + (size_t)256 * H;   // rows 256..383: edge_attr part

    float acc[8][8];
    {
        float bj[8];
        #pragma unroll
        for (int j = 0; j < 8; j++) bj[j] = be1[tx * 8 + j];
        #pragma unroll
        for (int i = 0; i < 8; i++)
            #pragma unroll
            for (int j = 0; j < 8; j++) acc[i][j] = bj[j];
    }

    for (int kc = 0; kc < 8; kc++) {
        const int k0 = kc * KC;
        float4 a0 = *(const float4*)(aEa + k0 + lh);
        float4 a1 = *(const float4*)(aEa + k0 + lh + 4);
        const float* wrow = We1c + (size_t)(k0 + bk) * H + bh;
        float4 b0 = *(const float4*)(wrow);
        float4 b1 = *(const float4*)(wrow + 4);
        __syncthreads();
        As[(lh + 0) * TM + le] = a0.x; As[(lh + 1) * TM + le] = a0.y;
        As[(lh + 2) * TM + le] = a0.z; As[(lh + 3) * TM + le] = a0.w;
        As[(lh + 4) * TM + le] = a1.x; As[(lh + 5) * TM + le] = a1.y;
        As[(lh + 6) * TM + le] = a1.z; As[(lh + 7) * TM + le] = a1.w;
        *(float4*)&Bs[bk * H + bh]     = b0;
        *(float4*)&Bs[bk * H + bh + 4] = b1;
        __syncthreads();
        #pragma unroll
        for (int kk = 0; kk < KC; kk++) {
            float af[8], bf[8];
            *(float4*)&af[0] = *(const float4*)&As[kk * TM + ty * 8];
            *(float4*)&af[4] = *(const float4*)&As[kk * TM + ty * 8 + 4];
            *(float4*)&bf[0] = *(const float4*)&Bs[kk * H + tx * 8];
            *(float4*)&bf[4] = *(const float4*)&Bs[kk * H + tx * 8 + 4];
            #pragma unroll
            for (int i = 0; i < 8; i++)
                #pragma unroll
                for (int j = 0; j < 8; j++)
                    acc[i][j] = fmaf(af[i], bf[j], acc[i][j]);
        }
    }

    // epilogue: gather P/Q, relu, scatter hidden + deg
    #pragma unroll
    for (int i = 0; i < 8; i++) {
        const int r = ty * 8 + i;
        if (e0 + r < nE) {
            const int cn = coli[r];
            const float* pp = g_P + (size_t)rowi[r] * H + tx * 8;
            const float* qq = g_Q + (size_t)cn * H + tx * 8;
            float4 p0 = *(const float4*)(pp);
            float4 p1 = *(const float4*)(pp + 4);
            float4 q0 = *(const float4*)(qq);
            float4 q1 = *(const float4*)(qq + 4);
            float* dst = g_aggH + (size_t)cn * H + tx * 8;
            red_add_v4(dst,
                       fmaxf(acc[i][0] + p0.x + q0.x, 0.f),
                       fmaxf(acc[i][1] + p0.y + q0.y, 0.f),
                       fmaxf(acc[i][2] + p0.z + q0.z, 0.f),
                       fmaxf(acc[i][3] + p0.w + q0.w, 0.f));
            red_add_v4(dst + 4,
                       fmaxf(acc[i][4] + p1.x + q1.x, 0.f),
                       fmaxf(acc[i][5] + p1.y + q1.y, 0.f),
                       fmaxf(acc[i][6] + p1.z + q1.z, 0.f),
                       fmaxf(acc[i][7] + p1.w + q1.w, 0.f));
            if (tx == 0) red_add_f32(g_deg + cn, 1.0f);
        }
    }
}

// ---------------------------------------------------------------------------
// Node pass: out = relu( x@Wn1_top + aggH@W' + deg*C + bn1 ) @ Wn2 + bn2
// ---------------------------------------------------------------------------
__global__ void __launch_bounds__(NTHR, 2)
node_kernel(const float* __restrict__ x,
            const float* __restrict__ Wn1, const float* __restrict__ bn1,
            const float* __restrict__ Wn2, const float* __restrict__ bn2,
            float* __restrict__ out, int nN)
{
    extern __shared__ float sm[];
    float* Bs  = sm;
    float* Hsm = sm + KC * H;
    float* As  = Hsm + TM * (H + 4);

    const int tid = threadIdx.x;
    const int tx  = tid & 15;
    const int ty  = tid >> 4;
    const int n0  = blockIdx.x * TM;

    const int le = tid >> 1;
    const int lh = (tid & 1) * 8;
    const size_t nrow = (size_t)min(n0 + le, nN - 1) * H;
    const float* aX = x + nrow;
    const float* aG = g_aggH + nrow;

    const int bk = tid >> 4;
    const int bh = (tid & 15) * 8;

    float acc[8][8];
    {
        float bj[8];
        #pragma unroll
        for (int j = 0; j < 8; j++) bj[j] = bn1[tx * 8 + j];
        #pragma unroll
        for (int i = 0; i < 8; i++)
            #pragma unroll
            for (int j = 0; j < 8; j++) acc[i][j] = bj[j];
    }

    for (int kc = 0; kc < 16; kc++) {
        const int k0 = (kc & 7) * KC;
        const float* abase = (kc < 8) ? aX : aG;
        const float* wrow  = (kc < 8)
            ? Wn1  + (size_t)(k0 + bk) * H + bh
            : g_Wp + (size_t)(k0 + bk) * H + bh;
        float4 a0 = *(const float4*)(abase + k0 + lh);
        float4 a1 = *(const float4*)(abase + k0 + lh + 4);
        float4 b0 = *(const float4*)(wrow);
        float4 b1 = *(const float4*)(wrow + 4);
        __syncthreads();
        As[(lh + 0) * TM + le] = a0.x; As[(lh + 1) * TM + le] = a0.y;
        As[(lh + 2) * TM + le] = a0.z; As[(lh + 3) * TM + le] = a0.w;
        As[(lh + 4) * TM + le] = a1.x; As[(lh + 5) * TM + le] = a1.y;
        As[(lh + 6) * TM + le] = a1.z; As[(lh + 7) * TM + le] = a1.w;
        *(float4*)&Bs[bk * H + bh]     = b0;
        *(float4*)&Bs[bk * H + bh + 4] = b1;
        __syncthreads();
        #pragma unroll
        for (int kk = 0; kk < KC; kk++) {
            float af[8], bf[8];
            *(float4*)&af[0] = *(const float4*)&As[kk * TM + ty * 8];
            *(float4*)&af[4] = *(const float4*)&As[kk * TM + ty * 8 + 4];
            *(float4*)&bf[0] = *(const float4*)&Bs[kk * H + tx * 8];
            *(float4*)&bf[4] = *(const float4*)&Bs[kk * H + tx * 8 + 4];
            #pragma unroll
            for (int i = 0; i < 8; i++)
                #pragma unroll
                for (int j = 0; j < 8; j++)
                    acc[i][j] = fmaf(af[i], bf[j], acc[i][j]);
        }
    }

    __syncthreads();
    // hidden = relu(acc + deg*C) -> Hsm
    {
        float cj[8];
        *(float4*)&cj[0] = *(const float4*)(g_C + tx * 8);
        *(float4*)&cj[4] = *(const float4*)(g_C + tx * 8 + 4);
        #pragma unroll
        for (int i = 0; i < 8; i++) {
            const int r = ty * 8 + i;
            const float dv = g_deg[min(n0 + r, nN - 1)];
            float* hp = &Hsm[r * (H + 4) + tx * 8];
            float4 h0, h1;
            h0.x = fmaxf(fmaf(dv, cj[0], acc[i][0]), 0.f);
            h0.y = fmaxf(fmaf(dv, cj[1], acc[i][1]), 0.f);
            h0.z = fmaxf(fmaf(dv, cj[2], acc[i][2]), 0.f);
            h0.w = fmaxf(fmaf(dv, cj[3], acc[i][3]), 0.f);
            h1.x = fmaxf(fmaf(dv, cj[4], acc[i][4]), 0.f);
            h1.y = fmaxf(fmaf(dv, cj[5], acc[i][5]), 0.f);
            h1.z = fmaxf(fmaf(dv, cj[6], acc[i][6]), 0.f);
            h1.w = fmaxf(fmaf(dv, cj[7], acc[i][7]), 0.f);
            *(float4*)(hp)     = h0;
            *(float4*)(hp + 4) = h1;
        }
    }
    {
        float bj[8];
        #pragma unroll
        for (int j = 0; j < 8; j++) bj[j] = bn2[tx * 8 + j];
        #pragma unroll
        for (int i = 0; i < 8; i++)
            #pragma unroll
            for (int j = 0; j < 8; j++) acc[i][j] = bj[j];
    }
    __syncthreads();

    for (int kc = 0; kc < 8; kc++) {
        const float* wrow = Wn2 + (size_t)(kc * KC + bk) * H + bh;
        float4 b0 = *(const float4*)(wrow);
        float4 b1 = *(const float4*)(wrow + 4);
        __syncthreads();
        *(float4*)&Bs[bk * H + bh]     = b0;
        *(float4*)&Bs[bk * H + bh + 4] = b1;
        __syncthreads();
        #pragma unroll
        for (int kk = 0; kk < KC; kk++) {
            const int k = kc * KC + kk;
            float bf[8];
            *(float4*)&bf[0] = *(const float4*)&Bs[kk * H + tx * 8];
            *(float4*)&bf[4] = *(const float4*)&Bs[kk * H + tx * 8 + 4];
            #pragma unroll
            for (int i = 0; i < 8; i++) {
                float a = Hsm[(ty * 8 + i) * (H + 4) + k];
                #pragma unroll
                for (int j = 0; j < 8; j++)
                    acc[i][j] = fmaf(a, bf[j], acc[i][j]);
            }
        }
    }

    #pragma unroll
    for (int i = 0; i < 8; i++) {
        const int r = ty * 8 + i;
        if (n0 + r < nN) {
            float* dst = out + (size_t)(n0 + r) * H + tx * 8;
            *(float4*)(dst)     = make_float4(acc[i][0], acc[i][1], acc[i][2], acc[i][3]);
            *(float4*)(dst + 4) = make_float4(acc[i][4], acc[i][5], acc[i][6], acc[i][7]);
        }
    }
}

extern "C" void kernel_launch(void* const* d_in, const int* in_sizes, int n_in,
                              void* d_out, int out_size)
{
    const float* x    = (const float*)d_in[0];
    const int*   eidx = (const int*)d_in[1];
    const float* ea   = (const float*)d_in[2];
    const float* We1  = (const float*)d_in[3];
    const float* be1  = (const float*)d_in[4];
    const float* We2  = (const float*)d_in[5];
    const float* be2  = (const float*)d_in[6];
    const float* Wn1  = (const float*)d_in[7];
    const float* bn1  = (const float*)d_in[8];
    const float* Wn2  = (const float*)d_in[9];
    const float* bn2  = (const float*)d_in[10];
    float* out = (float*)d_out;

    const int nN = in_sizes[0] / H;
    const int nE = in_sizes[1] / 2;

    const int node_smem = (KC * H + TM * (H + 4) + KC * TM) * (int)sizeof(float);
    const int gemm_smem = (KC * H + KC * TM) * (int)sizeof(float);
    cudaFuncSetAttribute(edge_kernel, cudaFuncAttributeMaxDynamicSharedMemorySize, gemm_smem);
    cudaFuncSetAttribute(node_kernel, cudaFuncAttributeMaxDynamicSharedMemorySize, node_smem);
    cudaFuncSetAttribute(prep_kernel, cudaFuncAttributeMaxDynamicSharedMemorySize, gemm_smem);

    const int n4  = nN * H / 4;
    const int nd4 = (nN + 3) / 4;
    zero_kernel<<<(n4 + nd4 + 255) / 256, 256>>>(n4, nd4);

    dim3 pq_grid((nN + TM - 1) / TM, 3);
    prep_kernel<<<pq_grid, NTHR, gemm_smem>>>(x, We1, We2, Wn1, be2, nN);

    edge_kernel<<<(nE + TM - 1) / TM, NTHR, gemm_smem>>>(ea, eidx, We1, be1, nE);
    node_kernel<<<(nN + TM - 1) / TM, NTHR, node_smem>>>(x, Wn1, bn1, Wn2, bn2, out, nN);
}

// round 12
// speedup vs baseline: 2.5234x; 1.0181x over previous
#include <cuda_runtime.h>
#include <cuda.h>
#include <cstdint>

#define H    128
#define TM   128
#define KC   16
#define NTHR 256

// ---------------- device scratch (allocation-free) ----------------
__device__ float g_aggH[50048 * H];   // segment-sum of hidden vectors
__device__ float g_deg[50048];        // in-degree (float)
__device__ float g_P[50048 * H];      // x @ We1[0:128]
__device__ float g_Q[50048 * H];      // x @ We1[128:256]
__device__ float g_Wp[H * H];         // We2 @ Wn1[128:256]
__device__ float g_C[H];              // be2 @ Wn1[128:256]

__device__ __forceinline__ void red_add_v4(float* addr, float a, float b, float c, float d) {
    asm volatile("red.global.add.v4.f32 [%0], {%1,%2,%3,%4};"
                 :: "l"(addr), "f"(a), "f"(b), "f"(c), "f"(d) : "memory");
}
__device__ __forceinline__ void red_add_f32(float* addr, float v) {
    asm volatile("red.global.add.f32 [%0], %1;" :: "l"(addr), "f"(v) : "memory");
}

__global__ void zero_kernel(int n4, int nd4) {
    int i = blockIdx.x * blockDim.x + threadIdx.x;
    if (i < n4)            ((float4*)g_aggH)[i] = make_float4(0.f, 0.f, 0.f, 0.f);
    else if (i < n4 + nd4) ((float4*)g_deg)[i - n4] = make_float4(0.f, 0.f, 0.f, 0.f);
}

// ---- shared inner-product microkernel (reads one k-slice) ----
#define MICRO_STEP(Asc, Bsc, kk)                                               \
    do {                                                                       \
        float af[8], bf[8];                                                    \
        *(float4*)&af[0] = *(const float4*)&(Asc)[(kk) * TM + ty * 8];         \
        *(float4*)&af[4] = *(const float4*)&(Asc)[(kk) * TM + ty * 8 + 4];     \
        *(float4*)&bf[0] = *(const float4*)&(Bsc)[(kk) * H + tx * 8];          \
        *(float4*)&bf[4] = *(const float4*)&(Bsc)[(kk) * H + tx * 8 + 4];      \
        _Pragma("unroll")                                                      \
        for (int i_ = 0; i_ < 8; i_++)                                         \
            _Pragma("unroll")                                                  \
            for (int j_ = 0; j_ < 8; j_++)                                     \
                acc[i_][j_] = fmaf(af[i_], bf[j_], acc[i_][j_]);               \
    } while (0)

#define STORE_AB(Asd, Bsd)                                                     \
    do {                                                                       \
        (Asd)[(lh + 0) * TM + le] = a0.x; (Asd)[(lh + 1) * TM + le] = a0.y;    \
        (Asd)[(lh + 2) * TM + le] = a0.z; (Asd)[(lh + 3) * TM + le] = a0.w;    \
        (Asd)[(lh + 4) * TM + le] = a1.x; (Asd)[(lh + 5) * TM + le] = a1.y;    \
        (Asd)[(lh + 6) * TM + le] = a1.z; (Asd)[(lh + 7) * TM + le] = a1.w;    \
        *(float4*)&(Bsd)[bk * H + bh]     = b0;                                \
        *(float4*)&(Bsd)[bk * H + bh + 4] = b1;                                \
    } while (0)

// ---------------------------------------------------------------------------
// prep: y=0 -> P = x@We1[0:128]; y=1 -> Q = x@We1[128:256];
//       y=2 (block x==0 only) -> W' = We2@Wn1_bot, C = be2@Wn1_bot
// ---------------------------------------------------------------------------
__global__ void __launch_bounds__(NTHR, 2)
prep_kernel(const float* __restrict__ x, const float* __restrict__ We1,
            const float* __restrict__ We2, const float* __restrict__ Wn1,
            const float* __restrict__ be2, int nN)
{
    if (blockIdx.y == 2 && blockIdx.x > 0) return;

    extern __shared__ float sm[];
    float* Bs = sm;                     // 2 x [KC][H]
    float* As = sm + 2 * KC * H;        // 2 x [KC][TM]

    const int tid = threadIdx.x;
    const int tx  = tid & 15;
    const int ty  = tid >> 4;
    const int n0  = blockIdx.x * TM;

    const float* Asrc;
    const float* W;
    float* outbuf;
    int rows;
    if (blockIdx.y == 0)      { Asrc = x;   W = We1;                 outbuf = g_P;  rows = nN; }
    else if (blockIdx.y == 1) { Asrc = x;   W = We1 + (size_t)H * H; outbuf = g_Q;  rows = nN; }
    else                      { Asrc = We2; W = Wn1 + (size_t)H * H; outbuf = g_Wp; rows = H;  }

    const int le = tid >> 1;
    const int lh = (tid & 1) * 8;
    const float* aX = Asrc + (size_t)min(n0 + le, rows - 1) * H;

    const int bk = tid >> 4;
    const int bh = (tid & 15) * 8;

    float acc[8][8];
    #pragma unroll
    for (int i = 0; i < 8; i++)
        #pragma unroll
        for (int j = 0; j < 8; j++) acc[i][j] = 0.f;

    // preload + store chunk 0
    float4 a0 = *(const float4*)(aX + lh);
    float4 a1 = *(const float4*)(aX + lh + 4);
    const float* wr0 = W + (size_t)bk * H + bh;
    float4 b0 = *(const float4*)(wr0);
    float4 b1 = *(const float4*)(wr0 + 4);
    STORE_AB(As, Bs);
    __syncthreads();

    for (int kc = 0; kc < 8; kc++) {
        float* Asc = As + (kc & 1) * KC * TM;
        float* Bsc = Bs + (kc & 1) * KC * H;
        if (kc < 7) {
            const int k0 = (kc + 1) * KC;
            a0 = *(const float4*)(aX + k0 + lh);
            a1 = *(const float4*)(aX + k0 + lh + 4);
            const float* wrow = W + (size_t)(k0 + bk) * H + bh;
            b0 = *(const float4*)(wrow);
            b1 = *(const float4*)(wrow + 4);
        }
        #pragma unroll
        for (int kk = 0; kk < KC; kk++) MICRO_STEP(Asc, Bsc, kk);
        if (kc < 7) {
            float* Asn = As + ((kc + 1) & 1) * KC * TM;
            float* Bsn = Bs + ((kc + 1) & 1) * KC * H;
            STORE_AB(Asn, Bsn);
        }
        __syncthreads();
    }

    #pragma unroll
    for (int i = 0; i < 8; i++) {
        const int r = ty * 8 + i;
        if (n0 + r < rows) {
            float* dst = outbuf + (size_t)(n0 + r) * H + tx * 8;
            *(float4*)(dst)     = make_float4(acc[i][0], acc[i][1], acc[i][2], acc[i][3]);
            *(float4*)(dst + 4) = make_float4(acc[i][4], acc[i][5], acc[i][6], acc[i][7]);
        }
    }

    if (blockIdx.y == 2 && tid < H) {
        float s = 0.f;
        #pragma unroll 8
        for (int m = 0; m < H; m++)
            s = fmaf(be2[m], Wn1[(size_t)(H + m) * H + tid], s);
        g_C[tid] = s;
    }
}

// ---------------------------------------------------------------------------
// Edge pass (stage-1 only, double-buffered):
//   hidden = relu( ea @ We1_c + P[row] + Q[col] + b1 )
//   red.add hidden into g_aggH[col]; red.add 1.0 into g_deg[col]
// ---------------------------------------------------------------------------
__global__ void __launch_bounds__(NTHR, 2)
edge_kernel(const float* __restrict__ ea, const int* __restrict__ eidx,
            const float* __restrict__ We1, const float* __restrict__ be1,
            int nE)
{
    extern __shared__ float sm[];
    float* Bs = sm;                     // 2 x [KC][H]
    float* As = sm + 2 * KC * H;        // 2 x [KC][TM]
    __shared__ int rowi[TM];
    __shared__ int coli[TM];

    const int tid = threadIdx.x;
    const int tx  = tid & 15;
    const int ty  = tid >> 4;
    const int e0  = blockIdx.x * TM;

    if (tid < TM) {
        int ec = min(e0 + tid, nE - 1);
        rowi[tid] = eidx[ec];
        coli[tid] = eidx[nE + ec];
    }

    const int le = tid >> 1;
    const int lh = (tid & 1) * 8;
    const float* aEa = ea + (size_t)min(e0 + le, nE - 1) * H;

    const int bk = tid >> 4;
    const int bh = (tid & 15) * 8;

    const float* We1c = We1 + (size_t)256 * H;   // rows 256..383: edge_attr part

    float acc[8][8];
    {
        float bj[8];
        #pragma unroll
        for (int j = 0; j < 8; j++) bj[j] = be1[tx * 8 + j];
        #pragma unroll
        for (int i = 0; i < 8; i++)
            #pragma unroll
            for (int j = 0; j < 8; j++) acc[i][j] = bj[j];
    }

    // preload + store chunk 0
    float4 a0 = *(const float4*)(aEa + lh);
    float4 a1 = *(const float4*)(aEa + lh + 4);
    const float* wr0 = We1c + (size_t)bk * H + bh;
    float4 b0 = *(const float4*)(wr0);
    float4 b1 = *(const float4*)(wr0 + 4);
    STORE_AB(As, Bs);
    __syncthreads();

    for (int kc = 0; kc < 8; kc++) {
        float* Asc = As + (kc & 1) * KC * TM;
        float* Bsc = Bs + (kc & 1) * KC * H;
        if (kc < 7) {
            const int k0 = (kc + 1) * KC;
            a0 = *(const float4*)(aEa + k0 + lh);
            a1 = *(const float4*)(aEa + k0 + lh + 4);
            const float* wrow = We1c + (size_t)(k0 + bk) * H + bh;
            b0 = *(const float4*)(wrow);
            b1 = *(const float4*)(wrow + 4);
        }
        #pragma unroll
        for (int kk = 0; kk < KC; kk++) MICRO_STEP(Asc, Bsc, kk);
        if (kc < 7) {
            float* Asn = As + ((kc + 1) & 1) * KC * TM;
            float* Bsn = Bs + ((kc + 1) & 1) * KC * H;
            STORE_AB(Asn, Bsn);
        }
        __syncthreads();
    }

    // epilogue: gather P/Q, relu, scatter hidden + deg
    #pragma unroll
    for (int i = 0; i < 8; i++) {
        const int r = ty * 8 + i;
        if (e0 + r < nE) {
            const int cn = coli[r];
            const float* pp = g_P + (size_t)rowi[r] * H + tx * 8;
            const float* qq = g_Q + (size_t)cn * H + tx * 8;
            float4 p0 = *(const float4*)(pp);
            float4 p1 = *(const float4*)(pp + 4);
            float4 q0 = *(const float4*)(qq);
            float4 q1 = *(const float4*)(qq + 4);
            float* dst = g_aggH + (size_t)cn * H + tx * 8;
            red_add_v4(dst,
                       fmaxf(acc[i][0] + p0.x + q0.x, 0.f),
                       fmaxf(acc[i][1] + p0.y + q0.y, 0.f),
                       fmaxf(acc[i][2] + p0.z + q0.z, 0.f),
                       fmaxf(acc[i][3] + p0.w + q0.w, 0.f));
            red_add_v4(dst + 4,
                       fmaxf(acc[i][4] + p1.x + q1.x, 0.f),
                       fmaxf(acc[i][5] + p1.y + q1.y, 0.f),
                       fmaxf(acc[i][6] + p1.z + q1.z, 0.f),
                       fmaxf(acc[i][7] + p1.w + q1.w, 0.f));
            if (tx == 0) red_add_f32(g_deg + cn, 1.0f);
        }
    }
}

// ---------------------------------------------------------------------------
// Node pass: out = relu( x@Wn1_top + aggH@W' + deg*C + bn1 ) @ Wn2 + bn2
// ---------------------------------------------------------------------------
__global__ void __launch_bounds__(NTHR, 2)
node_kernel(const float* __restrict__ x,
            const float* __restrict__ Wn1, const float* __restrict__ bn1,
            const float* __restrict__ Wn2, const float* __restrict__ bn2,
            float* __restrict__ out, int nN)
{
    extern __shared__ float sm[];
    float* Bs  = sm;                        // 2 x [KC][H]
    float* As  = sm + 2 * KC * H;           // 2 x [KC][TM]
    float* Hsm = As + 2 * KC * TM;          // [TM][H+4]

    const int tid = threadIdx.x;
    const int tx  = tid & 15;
    const int ty  = tid >> 4;
    const int n0  = blockIdx.x * TM;

    const int le = tid >> 1;
    const int lh = (tid & 1) * 8;
    const size_t nrow = (size_t)min(n0 + le, nN - 1) * H;
    const float* aX = x + nrow;
    const float* aG = g_aggH + nrow;

    const int bk = tid >> 4;
    const int bh = (tid & 15) * 8;

    float acc[8][8];
    {
        float bj[8];
        #pragma unroll
        for (int j = 0; j < 8; j++) bj[j] = bn1[tx * 8 + j];
        #pragma unroll
        for (int i = 0; i < 8; i++)
            #pragma unroll
            for (int j = 0; j < 8; j++) acc[i][j] = bj[j];
    }

    // preload + store chunk 0 (stage 1: 16 chunks, x then aggH; Wn1 then W')
    float4 a0 = *(const float4*)(aX + lh);
    float4 a1 = *(const float4*)(aX + lh + 4);
    const float* wr0 = Wn1 + (size_t)bk * H + bh;
    float4 b0 = *(const float4*)(wr0);
    float4 b1 = *(const float4*)(wr0 + 4);
    STORE_AB(As, Bs);
    __syncthreads();

    for (int kc = 0; kc < 16; kc++) {
        float* Asc = As + (kc & 1) * KC * TM;
        float* Bsc = Bs + (kc & 1) * KC * H;
        if (kc < 15) {
            const int kcn = kc + 1;
            const int k0 = (kcn & 7) * KC;
            const float* abase = (kcn < 8) ? aX : aG;
            const float* wrow  = (kcn < 8)
                ? Wn1  + (size_t)(k0 + bk) * H + bh
                : g_Wp + (size_t)(k0 + bk) * H + bh;
            a0 = *(const float4*)(abase + k0 + lh);
            a1 = *(const float4*)(abase + k0 + lh + 4);
            b0 = *(const float4*)(wrow);
            b1 = *(const float4*)(wrow + 4);
        }
        #pragma unroll
        for (int kk = 0; kk < KC; kk++) MICRO_STEP(Asc, Bsc, kk);
        if (kc < 15) {
            float* Asn = As + ((kc + 1) & 1) * KC * TM;
            float* Bsn = Bs + ((kc + 1) & 1) * KC * H;
            STORE_AB(Asn, Bsn);
        }
        __syncthreads();
    }

    // hidden = relu(acc + deg*C) -> Hsm
    {
        float cj[8];
        *(float4*)&cj[0] = *(const float4*)(g_C + tx * 8);
        *(float4*)&cj[4] = *(const float4*)(g_C + tx * 8 + 4);
        #pragma unroll
        for (int i = 0; i < 8; i++) {
            const int r = ty * 8 + i;
            const float dv = g_deg[min(n0 + r, nN - 1)];
            float* hp = &Hsm[r * (H + 4) + tx * 8];
            float4 h0, h1;
            h0.x = fmaxf(fmaf(dv, cj[0], acc[i][0]), 0.f);
            h0.y = fmaxf(fmaf(dv, cj[1], acc[i][1]), 0.f);
            h0.z = fmaxf(fmaf(dv, cj[2], acc[i][2]), 0.f);
            h0.w = fmaxf(fmaf(dv, cj[3], acc[i][3]), 0.f);
            h1.x = fmaxf(fmaf(dv, cj[4], acc[i][4]), 0.f);
            h1.y = fmaxf(fmaf(dv, cj[5], acc[i][5]), 0.f);
            h1.z = fmaxf(fmaf(dv, cj[6], acc[i][6]), 0.f);
            h1.w = fmaxf(fmaf(dv, cj[7], acc[i][7]), 0.f);
            *(float4*)(hp)     = h0;
            *(float4*)(hp + 4) = h1;
        }
    }
    {
        float bj[8];
        #pragma unroll
        for (int j = 0; j < 8; j++) bj[j] = bn2[tx * 8 + j];
        #pragma unroll
        for (int i = 0; i < 8; i++)
            #pragma unroll
            for (int j = 0; j < 8; j++) acc[i][j] = bj[j];
    }
    __syncthreads();

    // stage 2: Hsm @ Wn2 (B pipelined through the double buffer)
    {
        const float* wr = Wn2 + (size_t)bk * H + bh;
        b0 = *(const float4*)(wr);
        b1 = *(const float4*)(wr + 4);
        *(float4*)&Bs[bk * H + bh]     = b0;
        *(float4*)&Bs[bk * H + bh + 4] = b1;
    }
    __syncthreads();

    for (int kc = 0; kc < 8; kc++) {
        float* Bsc = Bs + (kc & 1) * KC * H;
        if (kc < 7) {
            const float* wrow = Wn2 + (size_t)((kc + 1) * KC + bk) * H + bh;
            b0 = *(const float4*)(wrow);
            b1 = *(const float4*)(wrow + 4);
        }
        #pragma unroll
        for (int kk = 0; kk < KC; kk++) {
            const int k = kc * KC + kk;
            float bf[8];
            *(float4*)&bf[0] = *(const float4*)&Bsc[kk * H + tx * 8];
            *(float4*)&bf[4] = *(const float4*)&Bsc[kk * H + tx * 8 + 4];
            #pragma unroll
            for (int i = 0; i < 8; i++) {
                float a = Hsm[(ty * 8 + i) * (H + 4) + k];
                #pragma unroll
                for (int j = 0; j < 8; j++)
                    acc[i][j] = fmaf(a, bf[j], acc[i][j]);
            }
        }
        if (kc < 7) {
            float* Bsn = Bs + ((kc + 1) & 1) * KC * H;
            *(float4*)&Bsn[bk * H + bh]     = b0;
            *(float4*)&Bsn[bk * H + bh + 4] = b1;
        }
        __syncthreads();
    }

    #pragma unroll
    for (int i = 0; i < 8; i++) {
        const int r = ty * 8 + i;
        if (n0 + r < nN) {
            float* dst = out + (size_t)(n0 + r) * H + tx * 8;
            *(float4*)(dst)     = make_float4(acc[i][0], acc[i][1], acc[i][2], acc[i][3]);
            *(float4*)(dst + 4) = make_float4(acc[i][4], acc[i][5], acc[i][6], acc[i][7]);
        }
    }
}

extern "C" void kernel_launch(void* const* d_in, const int* in_sizes, int n_in,
                              void* d_out, int out_size)
{
    const float* x    = (const float*)d_in[0];
    const int*   eidx = (const int*)d_in[1];
    const float* ea   = (const float*)d_in[2];
    const float* We1  = (const float*)d_in[3];
    const float* be1  = (const float*)d_in[4];
    const float* We2  = (const float*)d_in[5];
    const float* be2  = (const float*)d_in[6];
    const float* Wn1  = (const float*)d_in[7];
    const float* bn1  = (const float*)d_in[8];
    const float* Wn2  = (const float*)d_in[9];
    const float* bn2  = (const float*)d_in[10];
    float* out = (float*)d_out;

    const int nN = in_sizes[0] / H;
    const int nE = in_sizes[1] / 2;

    const int gemm_smem = 2 * (KC * H + KC * TM) * (int)sizeof(float);
    const int node_smem = gemm_smem + TM * (H + 4) * (int)sizeof(float);
    cudaFuncSetAttribute(edge_kernel, cudaFuncAttributeMaxDynamicSharedMemorySize, gemm_smem);
    cudaFuncSetAttribute(node_kernel, cudaFuncAttributeMaxDynamicSharedMemorySize, node_smem);
    cudaFuncSetAttribute(prep_kernel, cudaFuncAttributeMaxDynamicSharedMemorySize, gemm_smem);

    const int n4  = nN * H / 4;
    const int nd4 = (nN + 3) / 4;
    zero_kernel<<<(n4 + nd4 + 255) / 256, 256>>>(n4, nd4);

    dim3 pq_grid((nN + TM - 1) / TM, 3);
    prep_kernel<<<pq_grid, NTHR, gemm_smem>>>(x, We1, We2, Wn1, be2, nN);

    edge_kernel<<<(nE + TM - 1) / TM, NTHR, gemm_smem>>>(ea, eidx, We1, be1, nE);
    node_kernel<<<(nN + TM - 1) / TM, NTHR, node_smem>>>(x, Wn1, bn1, Wn2, bn2, out, nN);
}

// round 15
// speedup vs baseline: 2.6304x; 1.0424x over previous
#include <cuda_runtime.h>
#include <cuda.h>
#include <cstdint>

#define H    128
#define TM   128
#define KC   16
#define NTHR 256

// ---------------- device scratch (allocation-free) ----------------
__device__ float g_aggH[50048 * H];   // segment-sum of hidden vectors
__device__ float g_deg[50048];        // in-degree (float)
__device__ float g_P[50048 * H];      // x @ We1[0:128]
__device__ float g_Q[50048 * H];      // x @ We1[128:256]
__device__ float g_Wp[H * H];         // We2 @ Wn1[128:256]
__device__ float g_C[H];              // be2 @ Wn1[128:256]

__device__ __forceinline__ void red_add_v4(float* addr, float a, float b, float c, float d) {
    asm volatile("red.global.add.v4.f32 [%0], {%1,%2,%3,%4};"
                 :: "l"(addr), "f"(a), "f"(b), "f"(c), "f"(d) : "memory");
}
__device__ __forceinline__ void red_add_f32(float* addr, float v) {
    asm volatile("red.global.add.f32 [%0], %1;" :: "l"(addr), "f"(v) : "memory");
}

// ---- shared inner-product microkernel ----
#define MICRO_STEP(Asc, Bsc, kk)                                               \
    do {                                                                       \
        float af[8], bf[8];                                                    \
        *(float4*)&af[0] = *(const float4*)&(Asc)[(kk) * TM + ty * 8];         \
        *(float4*)&af[4] = *(const float4*)&(Asc)[(kk) * TM + ty * 8 + 4];     \
        *(float4*)&bf[0] = *(const float4*)&(Bsc)[(kk) * H + tx * 8];          \
        *(float4*)&bf[4] = *(const float4*)&(Bsc)[(kk) * H + tx * 8 + 4];      \
        _Pragma("unroll")                                                      \
        for (int i_ = 0; i_ < 8; i_++)                                         \
            _Pragma("unroll")                                                  \
            for (int j_ = 0; j_ < 8; j_++)                                     \
                acc[i_][j_] = fmaf(af[i_], bf[j_], acc[i_][j_]);               \
    } while (0)

#define STORE_AB(Asd, Bsd)                                                     \
    do {                                                                       \
        (Asd)[(lh + 0) * TM + le] = a0.x; (Asd)[(lh + 1) * TM + le] = a0.y;    \
        (Asd)[(lh + 2) * TM + le] = a0.z; (Asd)[(lh + 3) * TM + le] = a0.w;    \
        (Asd)[(lh + 4) * TM + le] = a1.x; (Asd)[(lh + 5) * TM + le] = a1.y;    \
        (Asd)[(lh + 6) * TM + le] = a1.z; (Asd)[(lh + 7) * TM + le] = a1.w;    \
        *(float4*)&(Bsd)[bk * H + bh]     = b0;                                \
        *(float4*)&(Bsd)[bk * H + bh + 4] = b1;                                \
    } while (0)

// ---------------------------------------------------------------------------
// prep: y=0 -> P = x@We1[0:128] (+ zero aggH/deg rows); y=1 -> Q;
//       y=2 (block x==0 only) -> W' = We2@Wn1_bot, C = be2@Wn1_bot
// ---------------------------------------------------------------------------
__global__ void __launch_bounds__(NTHR, 2)
prep_kernel(const float* __restrict__ x, const float* __restrict__ We1,
            const float* __restrict__ We2, const float* __restrict__ Wn1,
            const float* __restrict__ be2, int nN)
{
    if (blockIdx.y == 2 && blockIdx.x > 0) return;

    extern __shared__ float sm[];
    float* Bs = sm;                     // 2 x [KC][H]
    float* As = sm + 2 * KC * H;        // 2 x [KC][TM]

    const int tid = threadIdx.x;
    const int tx  = tid & 15;
    const int ty  = tid >> 4;
    const int n0  = blockIdx.x * TM;

    const float* Asrc;
    const float* W;
    float* outbuf;
    int rows;
    if (blockIdx.y == 0)      { Asrc = x;   W = We1;                 outbuf = g_P;  rows = nN; }
    else if (blockIdx.y == 1) { Asrc = x;   W = We1 + (size_t)H * H; outbuf = g_Q;  rows = nN; }
    else                      { Asrc = We2; W = Wn1 + (size_t)H * H; outbuf = g_Wp; rows = H;  }

    // y==0 blocks also zero aggH/deg for their node rows
    if (blockIdx.y == 0) {
        const float4 z = make_float4(0.f, 0.f, 0.f, 0.f);
        #pragma unroll
        for (int i = 0; i < 8; i++) {
            const int r = ty * 8 + i;
            if (n0 + r < nN)
                *(float4*)(g_aggH + (size_t)(n0 + r) * H + tx * 8) = z,
                *(float4*)(g_aggH + (size_t)(n0 + r) * H + tx * 8 + 4) = z;
        }
        if (tid < TM && n0 + tid < nN) g_deg[n0 + tid] = 0.f;
    }

    const int le = tid >> 1;
    const int lh = (tid & 1) * 8;
    const float* aX = Asrc + (size_t)min(n0 + le, rows - 1) * H;

    const int bk = tid >> 4;
    const int bh = (tid & 15) * 8;

    float acc[8][8];
    #pragma unroll
    for (int i = 0; i < 8; i++)
        #pragma unroll
        for (int j = 0; j < 8; j++) acc[i][j] = 0.f;

    float4 a0 = *(const float4*)(aX + lh);
    float4 a1 = *(const float4*)(aX + lh + 4);
    const float* wr0 = W + (size_t)bk * H + bh;
    float4 b0 = *(const float4*)(wr0);
    float4 b1 = *(const float4*)(wr0 + 4);
    STORE_AB(As, Bs);
    __syncthreads();

    for (int kc = 0; kc < 8; kc++) {
        float* Asc = As + (kc & 1) * KC * TM;
        float* Bsc = Bs + (kc & 1) * KC * H;
        if (kc < 7) {
            const int k0 = (kc + 1) * KC;
            a0 = *(const float4*)(aX + k0 + lh);
            a1 = *(const float4*)(aX + k0 + lh + 4);
            const float* wrow = W + (size_t)(k0 + bk) * H + bh;
            b0 = *(const float4*)(wrow);
            b1 = *(const float4*)(wrow + 4);
        }
        #pragma unroll
        for (int kk = 0; kk < KC; kk++) MICRO_STEP(Asc, Bsc, kk);
        if (kc < 7) {
            float* Asn = As + ((kc + 1) & 1) * KC * TM;
            float* Bsn = Bs + ((kc + 1) & 1) * KC * H;
            STORE_AB(Asn, Bsn);
        }
        __syncthreads();
    }

    #pragma unroll
    for (int i = 0; i < 8; i++) {
        const int r = ty * 8 + i;
        if (n0 + r < rows) {
            float* dst = outbuf + (size_t)(n0 + r) * H + tx * 8;
            *(float4*)(dst)     = make_float4(acc[i][0], acc[i][1], acc[i][2], acc[i][3]);
            *(float4*)(dst + 4) = make_float4(acc[i][4], acc[i][5], acc[i][6], acc[i][7]);
        }
    }

    if (blockIdx.y == 2 && tid < H) {
        float s = 0.f;
        #pragma unroll 8
        for (int m = 0; m < H; m++)
            s = fmaf(be2[m], Wn1[(size_t)(H + m) * H + tid], s);
        g_C[tid] = s;
    }
}

// ---------------------------------------------------------------------------
// Edge pass:
//   hidden = relu( ea @ We1_c + P[row] + Q[col] + b1 )
//   red.add hidden into g_aggH[col]; red.add 1.0 into g_deg[col]
// ea loads are evict-first (__ldcs); epilogue gathers are depth-2 pipelined.
// ---------------------------------------------------------------------------
__global__ void __launch_bounds__(NTHR, 2)
edge_kernel(const float* __restrict__ ea, const int* __restrict__ eidx,
            const float* __restrict__ We1, const float* __restrict__ be1,
            int nE)
{
    extern __shared__ float sm[];
    float* Bs = sm;                     // 2 x [KC][H]
    float* As = sm + 2 * KC * H;        // 2 x [KC][TM]
    __shared__ int rowi[TM];
    __shared__ int coli[TM];

    const int tid = threadIdx.x;
    const int tx  = tid & 15;
    const int ty  = tid >> 4;
    const int e0  = blockIdx.x * TM;

    if (tid < TM) {
        int ec = min(e0 + tid, nE - 1);
        rowi[tid] = eidx[ec];
        coli[tid] = eidx[nE + ec];
    }

    const int le = tid >> 1;
    const int lh = (tid & 1) * 8;
    const float* aEa = ea + (size_t)min(e0 + le, nE - 1) * H;

    const int bk = tid >> 4;
    const int bh = (tid & 15) * 8;

    const float* We1c = We1 + (size_t)256 * H;

    float acc[8][8];
    {
        float bj[8];
        #pragma unroll
        for (int j = 0; j < 8; j++) bj[j] = be1[tx * 8 + j];
        #pragma unroll
        for (int i = 0; i < 8; i++)
            #pragma unroll
            for (int j = 0; j < 8; j++) acc[i][j] = bj[j];
    }

    float4 a0 = __ldcs((const float4*)(aEa + lh));
    float4 a1 = __ldcs((const float4*)(aEa + lh + 4));
    const float* wr0 = We1c + (size_t)bk * H + bh;
    float4 b0 = *(const float4*)(wr0);
    float4 b1 = *(const float4*)(wr0 + 4);
    STORE_AB(As, Bs);
    __syncthreads();

    for (int kc = 0; kc < 8; kc++) {
        float* Asc = As + (kc & 1) * KC * TM;
        float* Bsc = Bs + (kc & 1) * KC * H;
        if (kc < 7) {
            const int k0 = (kc + 1) * KC;
            a0 = __ldcs((const float4*)(aEa + k0 + lh));
            a1 = __ldcs((const float4*)(aEa + k0 + lh + 4));
            const float* wrow = We1c + (size_t)(k0 + bk) * H + bh;
            b0 = *(const float4*)(wrow);
            b1 = *(const float4*)(wrow + 4);
        }
        #pragma unroll
        for (int kk = 0; kk < KC; kk++) MICRO_STEP(Asc, Bsc, kk);
        if (kc < 7) {
            float* Asn = As + ((kc + 1) & 1) * KC * TM;
            float* Bsn = Bs + ((kc + 1) & 1) * KC * H;
            STORE_AB(Asn, Bsn);
        }
        __syncthreads();
    }

    // ---- epilogue: depth-2 pipelined gather (P/Q), relu, scatter ----
    {
        int r = ty * 8;
        float4 p0 = __ldg((const float4*)(g_P + (size_t)rowi[r] * H + tx * 8));
        float4 p1 = __ldg((const float4*)(g_P + (size_t)rowi[r] * H + tx * 8 + 4));
        float4 q0 = __ldg((const float4*)(g_Q + (size_t)coli[r] * H + tx * 8));
        float4 q1 = __ldg((const float4*)(g_Q + (size_t)coli[r] * H + tx * 8 + 4));

        #pragma unroll
        for (int i = 0; i < 8; i++) {
            const int rc = ty * 8 + i;
            const int cn = coli[rc];
            const bool valid = (e0 + rc < nE);

            // deg atomic first (independent of gathers)
            if (valid && tx == 0) red_add_f32(g_deg + cn, 1.0f);

            // prefetch next row's P/Q before this row's REDGs
            float4 np0, np1, nq0, nq1;
            if (i < 7) {
                const int rn = rc + 1;
                np0 = __ldg((const float4*)(g_P + (size_t)rowi[rn] * H + tx * 8));
                np1 = __ldg((const float4*)(g_P + (size_t)rowi[rn] * H + tx * 8 + 4));
                nq0 = __ldg((const float4*)(g_Q + (size_t)coli[rn] * H + tx * 8));
                nq1 = __ldg((const float4*)(g_Q + (size_t)coli[rn] * H + tx * 8 + 4));
            }

            if (valid) {
                float* dst = g_aggH + (size_t)cn * H + tx * 8;
                red_add_v4(dst,
                           fmaxf(acc[i][0] + p0.x + q0.x, 0.f),
                           fmaxf(acc[i][1] + p0.y + q0.y, 0.f),
                           fmaxf(acc[i][2] + p0.z + q0.z, 0.f),
                           fmaxf(acc[i][3] + p0.w + q0.w, 0.f));
                red_add_v4(dst + 4,
                           fmaxf(acc[i][4] + p1.x + q1.x, 0.f),
                           fmaxf(acc[i][5] + p1.y + q1.y, 0.f),
                           fmaxf(acc[i][6] + p1.z + q1.z, 0.f),
                           fmaxf(acc[i][7] + p1.w + q1.w, 0.f));
            }
            if (i < 7) { p0 = np0; p1 = np1; q0 = nq0; q1 = nq1; }
        }
    }
}

// ---------------------------------------------------------------------------
// Node pass: out = relu( x@Wn1_top + aggH@W' + deg*C + bn1 ) @ Wn2 + bn2
// ---------------------------------------------------------------------------
__global__ void __launch_bounds__(NTHR, 2)
node_kernel(const float* __restrict__ x,
            const float* __restrict__ Wn1, const float* __restrict__ bn1,
            const float* __restrict__ Wn2, const float* __restrict__ bn2,
            float* __restrict__ out, int nN)
{
    extern __shared__ float sm[];
    float* Bs  = sm;                        // 2 x [KC][H]
    float* As  = sm + 2 * KC * H;           // 2 x [KC][TM]
    float* Hsm = As + 2 * KC * TM;          // [TM][H+4]

    const int tid = threadIdx.x;
    const int tx  = tid & 15;
    const int ty  = tid >> 4;
    const int n0  = blockIdx.x * TM;

    const int le = tid >> 1;
    const int lh = (tid & 1) * 8;
    const size_t nrow = (size_t)min(n0 + le, nN - 1) * H;
    const float* aX = x + nrow;
    const float* aG = g_aggH + nrow;

    const int bk = tid >> 4;
    const int bh = (tid & 15) * 8;

    float acc[8][8];
    {
        float bj[8];
        #pragma unroll
        for (int j = 0; j < 8; j++) bj[j] = bn1[tx * 8 + j];
        #pragma unroll
        for (int i = 0; i < 8; i++)
            #pragma unroll
            for (int j = 0; j < 8; j++) acc[i][j] = bj[j];
    }

    float4 a0 = *(const float4*)(aX + lh);
    float4 a1 = *(const float4*)(aX + lh + 4);
    const float* wr0 = Wn1 + (size_t)bk * H + bh;
    float4 b0 = *(const float4*)(wr0);
    float4 b1 = *(const float4*)(wr0 + 4);
    STORE_AB(As, Bs);
    __syncthreads();

    for (int kc = 0; kc < 16; kc++) {
        float* Asc = As + (kc & 1) * KC * TM;
        float* Bsc = Bs + (kc & 1) * KC * H;
        if (kc < 15) {
            const int kcn = kc + 1;
            const int k0 = (kcn & 7) * KC;
            const float* abase = (kcn < 8) ? aX : aG;
            const float* wrow  = (kcn < 8)
                ? Wn1  + (size_t)(k0 + bk) * H + bh
                : g_Wp + (size_t)(k0 + bk) * H + bh;
            a0 = *(const float4*)(abase + k0 + lh);
            a1 = *(const float4*)(abase + k0 + lh + 4);
            b0 = *(const float4*)(wrow);
            b1 = *(const float4*)(wrow + 4);
        }
        #pragma unroll
        for (int kk = 0; kk < KC; kk++) MICRO_STEP(Asc, Bsc, kk);
        if (kc < 15) {
            float* Asn = As + ((kc + 1) & 1) * KC * TM;
            float* Bsn = Bs + ((kc + 1) & 1) * KC * H;
            STORE_AB(Asn, Bsn);
        }
        __syncthreads();
    }

    {
        float cj[8];
        *(float4*)&cj[0] = *(const float4*)(g_C + tx * 8);
        *(float4*)&cj[4] = *(const float4*)(g_C + tx * 8 + 4);
        #pragma unroll
        for (int i = 0; i < 8; i++) {
            const int r = ty * 8 + i;
            const float dv = g_deg[min(n0 + r, nN - 1)];
            float* hp = &Hsm[r * (H + 4) + tx * 8];
            float4 h0, h1;
            h0.x = fmaxf(fmaf(dv, cj[0], acc[i][0]), 0.f);
            h0.y = fmaxf(fmaf(dv, cj[1], acc[i][1]), 0.f);
            h0.z = fmaxf(fmaf(dv, cj[2], acc[i][2]), 0.f);
            h0.w = fmaxf(fmaf(dv, cj[3], acc[i][3]), 0.f);
            h1.x = fmaxf(fmaf(dv, cj[4], acc[i][4]), 0.f);
            h1.y = fmaxf(fmaf(dv, cj[5], acc[i][5]), 0.f);
            h1.z = fmaxf(fmaf(dv, cj[6], acc[i][6]), 0.f);
            h1.w = fmaxf(fmaf(dv, cj[7], acc[i][7]), 0.f);
            *(float4*)(hp)     = h0;
            *(float4*)(hp + 4) = h1;
        }
    }
    {
        float bj[8];
        #pragma unroll
        for (int j = 0; j < 8; j++) bj[j] = bn2[tx * 8 + j];
        #pragma unroll
        for (int i = 0; i < 8; i++)
            #pragma unroll
            for (int j = 0; j < 8; j++) acc[i][j] = bj[j];
    }
    __syncthreads();

    {
        const float* wr = Wn2 + (size_t)bk * H + bh;
        b0 = *(const float4*)(wr);
        b1 = *(const float4*)(wr + 4);
        *(float4*)&Bs[bk * H + bh]     = b0;
        *(float4*)&Bs[bk * H + bh + 4] = b1;
    }
    __syncthreads();

    for (int kc = 0; kc < 8; kc++) {
        float* Bsc = Bs + (kc & 1) * KC * H;
        if (kc < 7) {
            const float* wrow = Wn2 + (size_t)((kc + 1) * KC + bk) * H + bh;
            b0 = *(const float4*)(wrow);
            b1 = *(const float4*)(wrow + 4);
        }
        #pragma unroll
        for (int kk = 0; kk < KC; kk++) {
            const int k = kc * KC + kk;
            float bf[8];
            *(float4*)&bf[0] = *(const float4*)&Bsc[kk * H + tx * 8];
            *(float4*)&bf[4] = *(const float4*)&Bsc[kk * H + tx * 8 + 4];
            #pragma unroll
            for (int i = 0; i < 8; i++) {
                float a = Hsm[(ty * 8 + i) * (H + 4) + k];
                #pragma unroll
                for (int j = 0; j < 8; j++)
                    acc[i][j] = fmaf(a, bf[j], acc[i][j]);
            }
        }
        if (kc < 7) {
            float* Bsn = Bs + ((kc + 1) & 1) * KC * H;
            *(float4*)&Bsn[bk * H + bh]     = b0;
            *(float4*)&Bsn[bk * H + bh + 4] = b1;
        }
        __syncthreads();
    }

    #pragma unroll
    for (int i = 0; i < 8; i++) {
        const int r = ty * 8 + i;
        if (n0 + r < nN) {
            float* dst = out + (size_t)(n0 + r) * H + tx * 8;
            *(float4*)(dst)     = make_float4(acc[i][0], acc[i][1], acc[i][2], acc[i][3]);
            *(float4*)(dst + 4) = make_float4(acc[i][4], acc[i][5], acc[i][6], acc[i][7]);
        }
    }
}

extern "C" void kernel_launch(void* const* d_in, const int* in_sizes, int n_in,
                              void* d_out, int out_size)
{
    const float* x    = (const float*)d_in[0];
    const int*   eidx = (const int*)d_in[1];
    const float* ea   = (const float*)d_in[2];
    const float* We1  = (const float*)d_in[3];
    const float* be1  = (const float*)d_in[4];
    const float* We2  = (const float*)d_in[5];
    const float* be2  = (const float*)d_in[6];
    const float* Wn1  = (const float*)d_in[7];
    const float* bn1  = (const float*)d_in[8];
    const float* Wn2  = (const float*)d_in[9];
    const float* bn2  = (const float*)d_in[10];
    float* out = (float*)d_out;

    const int nN = in_sizes[0] / H;
    const int nE = in_sizes[1] / 2;

    const int gemm_smem = 2 * (KC * H + KC * TM) * (int)sizeof(float);
    const int node_smem = gemm_smem + TM * (H + 4) * (int)sizeof(float);
    cudaFuncSetAttribute(edge_kernel, cudaFuncAttributeMaxDynamicSharedMemorySize, gemm_smem);
    cudaFuncSetAttribute(node_kernel, cudaFuncAttributeMaxDynamicSharedMemorySize, node_smem);
    cudaFuncSetAttribute(prep_kernel, cudaFuncAttributeMaxDynamicSharedMemorySize, gemm_smem);

    dim3 pq_grid((nN + TM - 1) / TM, 3);
    prep_kernel<<<pq_grid, NTHR, gemm_smem>>>(x, We1, We2, Wn1, be2, nN);

    edge_kernel<<<(nE + TM - 1) / TM, NTHR, gemm_smem>>>(ea, eidx, We1, be1, nE);
    node_kernel<<<(nN + TM - 1) / TM, NTHR, node_smem>>>(x, Wn1, bn1, Wn2, bn2, out, nN);
}